// round 4
// baseline (speedup 1.0000x reference)
#include <cuda_runtime.h>
#include <cuda_bf16.h>

// Problem constants: B=8, H=8, S=4096, D=64, DM=768
#define NB 8
#define NH 8
#define NS 4096
#define ND 64
#define NDM 768
#define NTOK 32752        // B * (S-2) = 8 * 4094
#define HD 512            // H * D

// Scratch (static __device__ arrays — no allocation allowed)
__device__ float g_G[NH * ND * ND];    // Gram of normalized Q_store, per head
__device__ float g_U[NH * ND * ND];    // Q_store^T V_store, per head
__device__ float g_T[NH * ND * ND];    // updated trace
__device__ float g_Wc[HD * NDM];       // combined weight: blockdiag(T) fused with W_out^T

// ---------------------------------------------------------------------------
// Kernel 0: zero G and U accumulators
// ---------------------------------------------------------------------------
__global__ void zero_kernel() {
    int i = blockIdx.x * blockDim.x + threadIdx.x;
    if (i < NH * ND * ND) { g_G[i] = 0.f; g_U[i] = 0.f; }
}

// ---------------------------------------------------------------------------
// Kernel 1: per-head Gram + cross accumulation.
//   G[h][p][r] += sum_{b,i} Qe[b,h,i,p] * Qe[b,h,i,r]
//   U[h][p][q] += sum_{b,i} Q [b,h,i,p] * V [b,h,i+2,q]
// grid = (chunks=32, H), block = 256 (16x16 threads, 4x4 per thread)
// ---------------------------------------------------------------------------
__global__ __launch_bounds__(256) void gram_kernel(const float* __restrict__ Q,
                                                   const float* __restrict__ V) {
    const int h = blockIdx.y;
    const int chunk = blockIdx.x;
    const int tid = threadIdx.x;
    const int ty = tid >> 4, tx = tid & 15;

    __shared__ float Qs[32][ND];
    __shared__ float Qe[32][ND];
    __shared__ float Vs[32][ND];
    __shared__ float s_inv[32];

    float accG[4][4] = {};
    float accU[4][4] = {};

    const int base = chunk * 1024;

    for (int t0 = base; t0 < base + 1024; t0 += 32) {
        // Load 32 tokens x 64 floats of Q and V (zero-pad past NTOK)
        #pragma unroll
        for (int i = 0; i < 2; i++) {
            int fid = tid + i * 256;          // [0,512) float4 slots
            int tok = fid >> 4;               // token within tile
            int d4  = (fid & 15) << 2;        // element offset
            int j = t0 + tok;                 // global token pair index
            float4 q = make_float4(0.f, 0.f, 0.f, 0.f);
            float4 v = make_float4(0.f, 0.f, 0.f, 0.f);
            if (j < NTOK) {
                int b  = j / (NS - 2);
                int ii = j - b * (NS - 2);
                long long baseQ = ((long long)(b * NH + h) * NS + ii) * ND + d4;
                long long baseV = ((long long)(b * NH + h) * NS + ii + 2) * ND + d4;
                q = *(const float4*)(Q + baseQ);
                v = *(const float4*)(V + baseV);
            }
            *(float4*)&Qs[tok][d4] = q;
            *(float4*)&Vs[tok][d4] = v;
        }
        __syncthreads();

        // Row norms (clip at EPS=1e-8), one token per thread for tid<32
        if (tid < 32) {
            float s = 0.f;
            #pragma unroll
            for (int d = 0; d < ND; d++) { float x = Qs[tid][d]; s += x * x; }
            float n = fmaxf(sqrtf(s), 1e-8f);
            s_inv[tid] = 1.0f / n;
        }
        __syncthreads();

        // Build normalized Qe
        #pragma unroll
        for (int i = 0; i < 8; i++) {
            int e = tid + i * 256;
            int tok = e >> 6, d = e & 63;
            Qe[tok][d] = Qs[tok][d] * s_inv[tok];
        }
        __syncthreads();

        // Rank-32 update of both 64x64 accumulators
        #pragma unroll 4
        for (int t = 0; t < 32; t++) {
            float4 ep = *(float4*)&Qe[t][ty << 2];
            float4 er = *(float4*)&Qe[t][tx << 2];
            float4 qp = *(float4*)&Qs[t][ty << 2];
            float4 vq = *(float4*)&Vs[t][tx << 2];
            float epv[4] = {ep.x, ep.y, ep.z, ep.w};
            float erv[4] = {er.x, er.y, er.z, er.w};
            float qpv[4] = {qp.x, qp.y, qp.z, qp.w};
            float vqv[4] = {vq.x, vq.y, vq.z, vq.w};
            #pragma unroll
            for (int i = 0; i < 4; i++)
                #pragma unroll
                for (int j = 0; j < 4; j++) {
                    accG[i][j] += epv[i] * erv[j];
                    accU[i][j] += qpv[i] * vqv[j];
                }
        }
        __syncthreads();
    }

    // Global accumulation (float atomics; validation is tolerance-based)
    #pragma unroll
    for (int i = 0; i < 4; i++)
        #pragma unroll
        for (int j = 0; j < 4; j++) {
            int p = (ty << 2) + i, r = (tx << 2) + j;
            atomicAdd(&g_G[(h * ND + p) * ND + r], accG[i][j]);
            atomicAdd(&g_U[(h * ND + p) * ND + r], accU[i][j]);
        }
}

// ---------------------------------------------------------------------------
// Kernel 2: T[h] = 0.99*trace - (0.99/denom)*G@trace + (0.1/denom)*U
// grid = H, block = 256
// ---------------------------------------------------------------------------
__global__ __launch_bounds__(256) void combine_kernel(const float* __restrict__ trace) {
    const int h = blockIdx.x;
    const int tid = threadIdx.x;
    __shared__ float Gs[ND][ND];
    __shared__ float Ts[ND][ND];
    for (int i = tid; i < ND * ND; i += 256) {
        Gs[i >> 6][i & 63] = g_G[h * ND * ND + i];
        Ts[i >> 6][i & 63] = trace[h * ND * ND + i];
    }
    __syncthreads();
    const float denom = (float)NTOK;
    const float c0 = 0.99f;
    const float c1 = 0.99f / denom;
    const float c2 = 0.1f / denom;
    for (int o = tid; o < ND * ND; o += 256) {
        int p = o >> 6, q = o & 63;
        float s = 0.f;
        #pragma unroll
        for (int r = 0; r < ND; r++) s += Gs[p][r] * Ts[r][q];
        g_T[h * ND * ND + o] = c0 * Ts[p][q] - c1 * s + c2 * g_U[h * ND * ND + o];
    }
}

// ---------------------------------------------------------------------------
// Kernel 3: fold trace into output weight.
//   Wc[h*64+p][m] = sum_q T[h][p][q] * W_out[m][h*64+q]
// grid = (H, 3), block = 256 (one m per thread)
// ---------------------------------------------------------------------------
__global__ __launch_bounds__(256) void wc_kernel(const float* __restrict__ W_out) {
    const int h = blockIdx.x;
    const int m = blockIdx.y * 256 + threadIdx.x;
    __shared__ float Ts[ND][ND];
    for (int i = threadIdx.x; i < ND * ND; i += 256)
        Ts[i >> 6][i & 63] = g_T[h * ND * ND + i];
    __syncthreads();
    float w[ND];
    #pragma unroll
    for (int q = 0; q < ND; q++) w[q] = W_out[m * HD + h * ND + q];
    for (int p = 0; p < ND; p++) {
        float s = 0.f;
        #pragma unroll
        for (int q = 0; q < ND; q++) s += Ts[p][q] * w[q];
        g_Wc[(h * ND + p) * NDM + m] = s;
    }
}

// ---------------------------------------------------------------------------
// Kernel 4: fused retrieval + projection as one GEMM.
//   out[(b*S+s)][m] = sum_{h,p} Q_addr[b,h,s,p] * Wc[h*64+p][m]
//   Q_addr gather (shift by 1, zero row at s==0) folded into A-tile load.
// 128x128x16 tiling, 8x8 per thread. grid = (M/128=256, N/128=6), block=256.
// ---------------------------------------------------------------------------
#define BM 128
#define BN 128
#define BK 16
__global__ __launch_bounds__(256) void gemm_kernel(const float* __restrict__ Q,
                                                   float* __restrict__ out) {
    __shared__ float As[BK][BM + 4];
    __shared__ float Bs[BK][BN];

    const int tid = threadIdx.x;
    const int ty = tid >> 4, tx = tid & 15;
    const int mBase = blockIdx.x * BM;
    const int nBase = blockIdx.y * BN;

    float acc[8][8] = {};

    for (int k0 = 0; k0 < HD; k0 += BK) {
        // --- load A tile (gather from Q with shift-by-1) ---
        #pragma unroll
        for (int i = 0; i < 2; i++) {
            int fid = tid + i * 256;          // [0,512)
            int m = fid >> 2;                 // row within tile
            int kk = (fid & 3) << 2;          // k offset within tile (x4)
            int c = k0 + kk;                  // global column: h*64+d
            int r = mBase + m;                // global row: b*4096+s
            int b = r >> 12, s = r & 4095;
            int hh = c >> 6, d = c & 63;
            float4 a = make_float4(0.f, 0.f, 0.f, 0.f);
            if (s > 0) {
                long long idx = (((long long)(b * NH + hh) * NS + (s - 1)) << 6) + d;
                a = *(const float4*)(Q + idx);
            }
            As[kk + 0][m] = a.x;
            As[kk + 1][m] = a.y;
            As[kk + 2][m] = a.z;
            As[kk + 3][m] = a.w;
        }
        // --- load B tile from Wc ---
        #pragma unroll
        for (int i = 0; i < 2; i++) {
            int fid = tid + i * 256;
            int k = fid >> 5;
            int n4 = (fid & 31) << 2;
            *(float4*)&Bs[k][n4] = *(const float4*)&g_Wc[(k0 + k) * NDM + nBase + n4];
        }
        __syncthreads();

        #pragma unroll
        for (int kk = 0; kk < BK; kk++) {
            float a[8], bq[8];
            *(float4*)&a[0]  = *(float4*)&As[kk][ty * 8];
            *(float4*)&a[4]  = *(float4*)&As[kk][ty * 8 + 4];
            *(float4*)&bq[0] = *(float4*)&Bs[kk][tx * 8];
            *(float4*)&bq[4] = *(float4*)&Bs[kk][tx * 8 + 4];
            #pragma unroll
            for (int i = 0; i < 8; i++)
                #pragma unroll
                for (int j = 0; j < 8; j++)
                    acc[i][j] += a[i] * bq[j];
        }
        __syncthreads();
    }

    // epilogue
    #pragma unroll
    for (int i = 0; i < 8; i++) {
        long long r = mBase + ty * 8 + i;
        float* o = out + r * NDM + nBase + tx * 8;
        *(float4*)(o)     = make_float4(acc[i][0], acc[i][1], acc[i][2], acc[i][3]);
        *(float4*)(o + 4) = make_float4(acc[i][4], acc[i][5], acc[i][6], acc[i][7]);
    }
}

// ---------------------------------------------------------------------------
extern "C" void kernel_launch(void* const* d_in, const int* in_sizes, int n_in,
                              void* d_out, int out_size) {
    const float* Q     = (const float*)d_in[0];  // (B,H,S,D)
    const float* V     = (const float*)d_in[1];  // (B,H,S,D)
    const float* trace = (const float*)d_in[2];  // (H,D,D)
    const float* W_out = (const float*)d_in[3];  // (DM, H*D)
    float* out = (float*)d_out;                  // (B,S,DM)

    zero_kernel<<<(NH * ND * ND + 255) / 256, 256>>>();
    {
        dim3 grid(32, NH);
        gram_kernel<<<grid, 256>>>(Q, V);
    }
    combine_kernel<<<NH, 256>>>(trace);
    {
        dim3 grid(NH, 3);
        wc_kernel<<<grid, 256>>>(W_out);
    }
    {
        dim3 grid((NB * NS) / BM, NDM / BN);
        gemm_kernel<<<grid, 256>>>(Q, out);
    }
}

// round 8
// speedup vs baseline: 1.8332x; 1.8332x over previous
#include <cuda_runtime.h>
#include <cuda_bf16.h>
#include <cstdint>

// Problem constants: B=8, H=8, S=4096, D=64, DM=768
#define NB 8
#define NH 8
#define NS 4096
#define ND 64
#define NDM 768
#define NTOK 32752        // B * (S-2)
#define HD 512            // H * D

// ---------------------------------------------------------------------------
// Scratch (static __device__ arrays — no allocation allowed)
// ---------------------------------------------------------------------------
__device__ float g_G[NH * ND * ND];
__device__ float g_U[NH * ND * ND];
__device__ float g_T[NH * ND * ND];
// Combined weight, N-major [NDM][HD], split into bf16 hi/lo
__device__ __align__(16) __nv_bfloat16 g_WcHi[NDM * HD];
__device__ __align__(16) __nv_bfloat16 g_WcLo[NDM * HD];

__device__ __forceinline__ uint32_t smem_to_u32(const void* smem_ptr) {
    uint32_t addr;
    asm("{ .reg .u64 tmp; cvta.to.shared.u64 tmp, %1; cvt.u32.u64 %0, tmp; }"
        : "=r"(addr) : "l"(smem_ptr));
    return addr;
}

// ldmatrix x4 (four 8x8 b16 matrices)
#define LDSM_X4(r, addr) \
    asm volatile("ldmatrix.sync.aligned.m8n8.x4.shared.b16 {%0,%1,%2,%3}, [%4];" \
        : "=r"((r)[0]), "=r"((r)[1]), "=r"((r)[2]), "=r"((r)[3]) : "r"(addr))

// mma m16n8k16 bf16 -> fp32
#define MMA16816(c, a, b0, b1) \
    asm volatile("mma.sync.aligned.m16n8k16.row.col.f32.bf16.bf16.f32 " \
        "{%0,%1,%2,%3}, {%4,%5,%6,%7}, {%8,%9}, {%0,%1,%2,%3};" \
        : "+f"((c)[0]), "+f"((c)[1]), "+f"((c)[2]), "+f"((c)[3]) \
        : "r"((a)[0]), "r"((a)[1]), "r"((a)[2]), "r"((a)[3]), "r"(b0), "r"(b1))

// ---------------------------------------------------------------------------
// Kernel 0: zero G and U accumulators
// ---------------------------------------------------------------------------
__global__ void zero_kernel() {
    int i = blockIdx.x * blockDim.x + threadIdx.x;
    if (i < NH * ND * ND) { g_G[i] = 0.f; g_U[i] = 0.f; }
}

// ---------------------------------------------------------------------------
// Kernel 1: per-head Gram + cross accumulation (unchanged — passed in R4).
// ---------------------------------------------------------------------------
__global__ __launch_bounds__(256) void gram_kernel(const float* __restrict__ Q,
                                                   const float* __restrict__ V) {
    const int h = blockIdx.y;
    const int chunk = blockIdx.x;
    const int tid = threadIdx.x;
    const int ty = tid >> 4, tx = tid & 15;

    __shared__ float Qs[32][ND];
    __shared__ float Qe[32][ND];
    __shared__ float Vs[32][ND];
    __shared__ float s_inv[32];

    float accG[4][4] = {};
    float accU[4][4] = {};

    const int base = chunk * 1024;

    for (int t0 = base; t0 < base + 1024; t0 += 32) {
        #pragma unroll
        for (int i = 0; i < 2; i++) {
            int fid = tid + i * 256;
            int tok = fid >> 4;
            int d4  = (fid & 15) << 2;
            int j = t0 + tok;
            float4 q = make_float4(0.f, 0.f, 0.f, 0.f);
            float4 v = make_float4(0.f, 0.f, 0.f, 0.f);
            if (j < NTOK) {
                int b  = j / (NS - 2);
                int ii = j - b * (NS - 2);
                long long baseQ = ((long long)(b * NH + h) * NS + ii) * ND + d4;
                long long baseV = ((long long)(b * NH + h) * NS + ii + 2) * ND + d4;
                q = *(const float4*)(Q + baseQ);
                v = *(const float4*)(V + baseV);
            }
            *(float4*)&Qs[tok][d4] = q;
            *(float4*)&Vs[tok][d4] = v;
        }
        __syncthreads();

        if (tid < 32) {
            float s = 0.f;
            #pragma unroll
            for (int d = 0; d < ND; d++) { float x = Qs[tid][d]; s += x * x; }
            float n = fmaxf(sqrtf(s), 1e-8f);
            s_inv[tid] = 1.0f / n;
        }
        __syncthreads();

        #pragma unroll
        for (int i = 0; i < 8; i++) {
            int e = tid + i * 256;
            int tok = e >> 6, d = e & 63;
            Qe[tok][d] = Qs[tok][d] * s_inv[tok];
        }
        __syncthreads();

        #pragma unroll 4
        for (int t = 0; t < 32; t++) {
            float4 ep = *(float4*)&Qe[t][ty << 2];
            float4 er = *(float4*)&Qe[t][tx << 2];
            float4 qp = *(float4*)&Qs[t][ty << 2];
            float4 vq = *(float4*)&Vs[t][tx << 2];
            float epv[4] = {ep.x, ep.y, ep.z, ep.w};
            float erv[4] = {er.x, er.y, er.z, er.w};
            float qpv[4] = {qp.x, qp.y, qp.z, qp.w};
            float vqv[4] = {vq.x, vq.y, vq.z, vq.w};
            #pragma unroll
            for (int i = 0; i < 4; i++)
                #pragma unroll
                for (int j = 0; j < 4; j++) {
                    accG[i][j] += epv[i] * erv[j];
                    accU[i][j] += qpv[i] * vqv[j];
                }
        }
        __syncthreads();
    }

    #pragma unroll
    for (int i = 0; i < 4; i++)
        #pragma unroll
        for (int j = 0; j < 4; j++) {
            int p = (ty << 2) + i, r = (tx << 2) + j;
            atomicAdd(&g_G[(h * ND + p) * ND + r], accG[i][j]);
            atomicAdd(&g_U[(h * ND + p) * ND + r], accU[i][j]);
        }
}

// ---------------------------------------------------------------------------
// Kernel 2: T[h] = 0.99*trace - (0.99/denom)*G@trace + (0.1/denom)*U
// ---------------------------------------------------------------------------
__global__ __launch_bounds__(256) void combine_kernel(const float* __restrict__ trace) {
    const int h = blockIdx.x;
    const int tid = threadIdx.x;
    __shared__ float Gs[ND][ND];
    __shared__ float Ts[ND][ND];
    for (int i = tid; i < ND * ND; i += 256) {
        Gs[i >> 6][i & 63] = g_G[h * ND * ND + i];
        Ts[i >> 6][i & 63] = trace[h * ND * ND + i];
    }
    __syncthreads();
    const float denom = (float)NTOK;
    const float c0 = 0.99f;
    const float c1 = 0.99f / denom;
    const float c2 = 0.1f / denom;
    for (int o = tid; o < ND * ND; o += 256) {
        int p = o >> 6, q = o & 63;
        float s = 0.f;
        #pragma unroll
        for (int r = 0; r < ND; r++) s += Gs[p][r] * Ts[r][q];
        g_T[h * ND * ND + o] = c0 * Ts[p][q] - c1 * s + c2 * g_U[h * ND * ND + o];
    }
}

// ---------------------------------------------------------------------------
// Kernel 3: fold trace into output weight, N-major, split into bf16 hi/lo.
//   Wc[m][h*64+p] = sum_q T[h][p][q] * W_out[m][h*64+q]
// grid = (H=8, NDM/64=12), block = 256
// ---------------------------------------------------------------------------
__global__ __launch_bounds__(256) void wc_kernel(const float* __restrict__ W_out) {
    const int h = blockIdx.x;
    const int mb = blockIdx.y * 64;
    __shared__ float Ts[ND][ND];
    for (int i = threadIdx.x; i < ND * ND; i += 256)
        Ts[i >> 6][i & 63] = g_T[h * ND * ND + i];
    __syncthreads();

    const int m = mb + (threadIdx.x >> 2);
    const int p0 = (threadIdx.x & 3) * 16;
    float w[ND];
    #pragma unroll
    for (int q = 0; q < ND; q++) w[q] = W_out[(long long)m * HD + h * ND + q];
    #pragma unroll
    for (int pi = 0; pi < 16; pi++) {
        int p = p0 + pi;
        float s = 0.f;
        #pragma unroll
        for (int q = 0; q < ND; q++) s += Ts[p][q] * w[q];
        __nv_bfloat16 hi = __float2bfloat16_rn(s);
        __nv_bfloat16 lo = __float2bfloat16_rn(s - __bfloat162float(hi));
        g_WcHi[(long long)m * HD + h * ND + p] = hi;
        g_WcLo[(long long)m * HD + h * ND + p] = lo;
    }
}

// ---------------------------------------------------------------------------
// Kernel 4: fused retrieval+projection GEMM via mma.sync (bf16 split, fp32 acc)
//   out[b*S+s][m] = sum_k Q_addr_flat[row][k] * Wc[m][k]
// CTA tile 128x128, K-block 64 (one head). 8 warps of 32x64.
// SMEM tiles padded to 72 bf16 (144 B) rows for conflict-free ldmatrix.
// ---------------------------------------------------------------------------
#define APITCH 72            // bf16 elements per smem row (64 + 8 pad)
#define TILE_B (128 * APITCH * 2)   // 18432 bytes per tile
#define SA_H 0
#define SA_L (TILE_B)
#define SB_H (2 * TILE_B)
#define SB_L (3 * TILE_B)
#define GEMM_SMEM (4 * TILE_B)      // 73728 bytes

__global__ void __launch_bounds__(256, 2) gemm_mma_kernel(const float* __restrict__ Q,
                                                          float* __restrict__ out) {
    extern __shared__ char smem[];
    const uint32_t sbase = smem_to_u32(smem);
    const int tid = threadIdx.x;
    const int lane = tid & 31, wid = tid >> 5;
    const int warpM = (wid & 3) * 32;     // 4 warps cover 128 M
    const int warpN = (wid >> 2) * 64;    // 2 warps cover 128 N
    const int mBase = blockIdx.x * 128;
    const int nBase = blockIdx.y * 128;

    float acc[2][8][4] = {};

    // ldmatrix per-lane byte offsets within a tile
    // A x4: lanes 0-15 -> rows (lane&15), k+0; lanes 16-31 -> rows (lane&15), k+8
    const uint32_t aoff = (uint32_t)(warpM + (lane & 15)) * 144 + (lane >> 4) * 16;
    // B x4: lanes 0-7 n+lane k0 | 8-15 n+(lane&7) k8 | 16-23 n+8+(lane&7) k0 | 24-31 n+8+(lane&7) k8
    const uint32_t boff = (uint32_t)(warpN + ((lane >> 4) << 3) + (lane & 7)) * 144
                        + (((lane >> 3) & 1) * 16);

    #pragma unroll 1
    for (int kb = 0; kb < 8; kb++) {
        // ---- load A tile: gather 128x64 fp32 (shift-by-1), split to bf16 hi/lo ----
        #pragma unroll
        for (int i = 0; i < 8; i++) {
            int fid = tid + i * 256;          // [0,2048) float4 slots
            int m = fid >> 4;
            int d4 = (fid & 15) << 2;
            int r = mBase + m;
            int b = r >> 12, s = r & 4095;
            float4 q = make_float4(0.f, 0.f, 0.f, 0.f);
            if (s > 0) {
                const float* p = Q + ((((long long)(b * NH + kb)) * NS + (s - 1)) << 6) + d4;
                q = *(const float4*)p;
            }
            __nv_bfloat16 x0 = __float2bfloat16_rn(q.x);
            __nv_bfloat16 x1 = __float2bfloat16_rn(q.y);
            __nv_bfloat16 x2 = __float2bfloat16_rn(q.z);
            __nv_bfloat16 x3 = __float2bfloat16_rn(q.w);
            __nv_bfloat16 y0 = __float2bfloat16_rn(q.x - __bfloat162float(x0));
            __nv_bfloat16 y1 = __float2bfloat16_rn(q.y - __bfloat162float(x1));
            __nv_bfloat16 y2 = __float2bfloat16_rn(q.z - __bfloat162float(x2));
            __nv_bfloat16 y3 = __float2bfloat16_rn(q.w - __bfloat162float(x3));
            unsigned h01 = ((unsigned)__bfloat16_as_ushort(x1) << 16) | __bfloat16_as_ushort(x0);
            unsigned h23 = ((unsigned)__bfloat16_as_ushort(x3) << 16) | __bfloat16_as_ushort(x2);
            unsigned l01 = ((unsigned)__bfloat16_as_ushort(y1) << 16) | __bfloat16_as_ushort(y0);
            unsigned l23 = ((unsigned)__bfloat16_as_ushort(y3) << 16) | __bfloat16_as_ushort(y2);
            unsigned off = (unsigned)m * 144 + (unsigned)d4 * 2;
            *(uint2*)(smem + SA_H + off) = make_uint2(h01, h23);
            *(uint2*)(smem + SA_L + off) = make_uint2(l01, l23);
        }
        // ---- load B tile: 128 n-rows x 64 k bf16 (pre-split in gmem) ----
        #pragma unroll
        for (int i = 0; i < 4; i++) {
            int fid = tid + i * 256;          // [0,1024) uint4 slots
            int n = fid >> 3;
            int c8 = (fid & 7) << 3;          // k offset (8 bf16)
            long long g = (long long)(nBase + n) * HD + kb * 64 + c8;
            uint4 vh = *(const uint4*)(g_WcHi + g);
            uint4 vl = *(const uint4*)(g_WcLo + g);
            unsigned off = (unsigned)n * 144 + (unsigned)c8 * 2;
            *(uint4*)(smem + SB_H + off) = vh;
            *(uint4*)(smem + SB_L + off) = vl;
        }
        __syncthreads();

        // ---- MMA over 4 k16 steps, 3 products ----
        #pragma unroll
        for (int ks = 0; ks < 4; ks++) {
            uint32_t aH = sbase + SA_H + aoff + ks * 32;
            uint32_t aL = sbase + SA_L + aoff + ks * 32;
            uint32_t ah[2][4], al[2][4];
            LDSM_X4(ah[0], aH);
            LDSM_X4(ah[1], aH + 16 * 144);
            LDSM_X4(al[0], aL);
            LDSM_X4(al[1], aL + 16 * 144);
            #pragma unroll
            for (int nt = 0; nt < 4; nt++) {
                uint32_t bH = sbase + SB_H + boff + ks * 32 + nt * 16 * 144;
                uint32_t bL = sbase + SB_L + boff + ks * 32 + nt * 16 * 144;
                uint32_t bh[4], bl[4];
                LDSM_X4(bh, bH);
                LDSM_X4(bl, bL);
                #pragma unroll
                for (int mt = 0; mt < 2; mt++) {
                    MMA16816(acc[mt][2 * nt],     ah[mt], bh[0], bh[1]);
                    MMA16816(acc[mt][2 * nt + 1], ah[mt], bh[2], bh[3]);
                    MMA16816(acc[mt][2 * nt],     ah[mt], bl[0], bl[1]);
                    MMA16816(acc[mt][2 * nt + 1], ah[mt], bl[2], bl[3]);
                    MMA16816(acc[mt][2 * nt],     al[mt], bh[0], bh[1]);
                    MMA16816(acc[mt][2 * nt + 1], al[mt], bh[2], bh[3]);
                }
            }
        }
        __syncthreads();
    }

    // ---- epilogue: acc -> out ----
    #pragma unroll
    for (int mt = 0; mt < 2; mt++) {
        #pragma unroll
        for (int j = 0; j < 8; j++) {
            long long row = mBase + warpM + mt * 16 + (lane >> 2);
            int col = nBase + warpN + j * 8 + (lane & 3) * 2;
            float* o = out + row * NDM + col;
            *(float2*)o = make_float2(acc[mt][j][0], acc[mt][j][1]);
            *(float2*)(o + 8LL * NDM) = make_float2(acc[mt][j][2], acc[mt][j][3]);
        }
    }
}

// ---------------------------------------------------------------------------
extern "C" void kernel_launch(void* const* d_in, const int* in_sizes, int n_in,
                              void* d_out, int out_size) {
    const float* Q     = (const float*)d_in[0];  // (B,H,S,D)
    const float* V     = (const float*)d_in[1];  // (B,H,S,D)
    const float* trace = (const float*)d_in[2];  // (H,D,D)
    const float* W_out = (const float*)d_in[3];  // (DM, H*D)
    float* out = (float*)d_out;                  // (B,S,DM)

    cudaFuncSetAttribute(gemm_mma_kernel,
                         cudaFuncAttributeMaxDynamicSharedMemorySize, GEMM_SMEM);

    zero_kernel<<<(NH * ND * ND + 255) / 256, 256>>>();
    {
        dim3 grid(32, NH);
        gram_kernel<<<grid, 256>>>(Q, V);
    }
    combine_kernel<<<NH, 256>>>(trace);
    {
        dim3 grid(NH, NDM / 64);
        wc_kernel<<<grid, 256>>>(W_out);
    }
    {
        dim3 grid((NB * NS) / 128, NDM / 128);
        gemm_mma_kernel<<<grid, 256, GEMM_SMEM>>>(Q, out);
    }
}

// round 11
// speedup vs baseline: 2.4347x; 1.3281x over previous
#include <cuda_runtime.h>
#include <cuda_bf16.h>
#include <cstdint>

// Problem constants: B=8, H=8, S=4096, D=64, DM=768
#define NB 8
#define NH 8
#define NS 4096
#define ND 64
#define NDM 768
#define NTOK 32752        // B * (S-2)
#define HD 512            // H * D
#define NROW 32768        // B * S

// ---------------------------------------------------------------------------
// Scratch (static __device__ arrays — no allocation allowed)
// ---------------------------------------------------------------------------
__device__ float g_G[NH * ND * ND];
__device__ float g_U[NH * ND * ND];
__device__ float g_T[NH * ND * ND];
// Combined weight, N-major [NDM][HD], bf16 hi/lo
__device__ __align__(16) __nv_bfloat16 g_WcHi[NDM * HD];
__device__ __align__(16) __nv_bfloat16 g_WcLo[NDM * HD];
// Pre-split A = Q_addr (shift-by-1), [NROW][HD], bf16 hi/lo
__device__ __align__(16) __nv_bfloat16 g_AHi[NROW * HD];
__device__ __align__(16) __nv_bfloat16 g_ALo[NROW * HD];

__device__ __forceinline__ uint32_t smem_to_u32(const void* smem_ptr) {
    uint32_t addr;
    asm("{ .reg .u64 tmp; cvta.to.shared.u64 tmp, %1; cvt.u32.u64 %0, tmp; }"
        : "=r"(addr) : "l"(smem_ptr));
    return addr;
}

#define LDSM_X4(r, addr) \
    asm volatile("ldmatrix.sync.aligned.m8n8.x4.shared.b16 {%0,%1,%2,%3}, [%4];" \
        : "=r"((r)[0]), "=r"((r)[1]), "=r"((r)[2]), "=r"((r)[3]) : "r"(addr))

#define LDSM_X4_T(r, addr) \
    asm volatile("ldmatrix.sync.aligned.m8n8.x4.trans.shared.b16 {%0,%1,%2,%3}, [%4];" \
        : "=r"((r)[0]), "=r"((r)[1]), "=r"((r)[2]), "=r"((r)[3]) : "r"(addr))

#define MMA16816(c, a, b0, b1) \
    asm volatile("mma.sync.aligned.m16n8k16.row.col.f32.bf16.bf16.f32 " \
        "{%0,%1,%2,%3}, {%4,%5,%6,%7}, {%8,%9}, {%0,%1,%2,%3};" \
        : "+f"((c)[0]), "+f"((c)[1]), "+f"((c)[2]), "+f"((c)[3]) \
        : "r"((a)[0]), "r"((a)[1]), "r"((a)[2]), "r"((a)[3]), "r"(b0), "r"(b1))

#define CP_ASYNC16(dst, src) \
    asm volatile("cp.async.cg.shared.global [%0], [%1], 16;" :: "r"(dst), "l"(src))
#define CP_COMMIT() asm volatile("cp.async.commit_group;")
#define CP_WAIT(n)  asm volatile("cp.async.wait_group %0;" :: "n"(n))

__device__ __forceinline__ unsigned pack_bf16(float a, float b) {
    __nv_bfloat16 x = __float2bfloat16_rn(a), y = __float2bfloat16_rn(b);
    return ((unsigned)__bfloat16_as_ushort(y) << 16) | __bfloat16_as_ushort(x);
}

// ---------------------------------------------------------------------------
// Kernel 0: zero G and U accumulators
// ---------------------------------------------------------------------------
__global__ void zero_kernel() {
    int i = blockIdx.x * blockDim.x + threadIdx.x;
    if (i < NH * ND * ND) { g_G[i] = 0.f; g_U[i] = 0.f; }
}

// ---------------------------------------------------------------------------
// Kernel P: pre-split A = Q_addr (shift-by-1 rows of Q) into bf16 hi/lo.
//   A[r][h*64+d] = Q[b,h,s-1,d], zero at s==0;  r = b*4096+s
// grid = NROW*HD/4/256 = 16384 blocks
// ---------------------------------------------------------------------------
__global__ __launch_bounds__(256) void prep_a_kernel(const float* __restrict__ Q) {
    int fid = blockIdx.x * 256 + threadIdx.x;   // float4 slot
    int r = fid >> 7;
    int c4 = fid & 127;
    int b = r >> 12, s = r & 4095;
    int h = c4 >> 4, d4 = (c4 & 15) << 2;
    float4 q = make_float4(0.f, 0.f, 0.f, 0.f);
    if (s > 0) {
        const float* p = Q + ((((long long)(b * NH + h)) * NS + (s - 1)) << 6) + d4;
        q = *(const float4*)p;
    }
    __nv_bfloat16 x0 = __float2bfloat16_rn(q.x), x1 = __float2bfloat16_rn(q.y);
    __nv_bfloat16 x2 = __float2bfloat16_rn(q.z), x3 = __float2bfloat16_rn(q.w);
    unsigned h01 = ((unsigned)__bfloat16_as_ushort(x1) << 16) | __bfloat16_as_ushort(x0);
    unsigned h23 = ((unsigned)__bfloat16_as_ushort(x3) << 16) | __bfloat16_as_ushort(x2);
    unsigned l01 = pack_bf16(q.x - __bfloat162float(x0), q.y - __bfloat162float(x1));
    unsigned l23 = pack_bf16(q.z - __bfloat162float(x2), q.w - __bfloat162float(x3));
    long long o = (long long)r * HD + c4 * 4;
    *(uint2*)(g_AHi + o) = make_uint2(h01, h23);
    *(uint2*)(g_ALo + o) = make_uint2(l01, l23);
}

// ---------------------------------------------------------------------------
// Kernel 1: Gram + cross accumulation on tensor cores.
//   G[h] += Qe^T Qe ; U[h] += Q^T Vshift  (K = tokens, bf16 inputs, fp32 acc)
// grid = (32 chunks, H), block 256 (8 warps: 0-3 G, 4-7 U). 1024 tokens/chunk.
// ---------------------------------------------------------------------------
#define GP 72               // smem pitch (bf16 elems), 144 B
#define G_QE 0
#define G_QB (128 * GP * 2)
#define G_VB (2 * 128 * GP * 2)
#define GRAM_SMEM (3 * 128 * GP * 2)   // 55296 B

__global__ void __launch_bounds__(256) gram_tc_kernel(const float* __restrict__ Q,
                                                      const float* __restrict__ V) {
    extern __shared__ char smem[];
    const uint32_t sbase = smem_to_u32(smem);
    const int h = blockIdx.y;
    const int tid = threadIdx.x;
    const int lane = tid & 31, wid = tid >> 5;
    const int wg = wid & 3;
    const int mT = (wg & 1) * 32, nT = (wg >> 1) * 32;

    // lane address components for trans ldmatrix
    const int krowA = ((lane >> 4) << 3) + (lane & 7);
    const int dcolA = ((lane >> 3) & 1) << 3;
    const int krowB = (((lane >> 3) & 1) << 3) + (lane & 7);
    const int ncolB = (lane >> 4) << 3;

    float acc[2][4][4] = {};

    const int tok0 = blockIdx.x * 1024;

    #pragma unroll 1
    for (int sub = 0; sub < 8; sub++) {
        // ---- prepare 128-token subtile: Qe, Qb, Vb (bf16) ----
        {
            int t = tid >> 1;            // token within subtile
            int half = tid & 1;          // d half: 0 -> 0..31, 1 -> 32..63
            int j = tok0 + sub * 128 + t;
            float qv[32], vv[32];
            if (j < NTOK) {
                int b = j / (NS - 2);
                int ii = j - b * (NS - 2);
                const float* qp = Q + ((((long long)(b * NH + h)) * NS + ii) << 6) + half * 32;
                const float* vp = V + ((((long long)(b * NH + h)) * NS + ii + 2) << 6) + half * 32;
                #pragma unroll
                for (int i = 0; i < 8; i++) {
                    *(float4*)&qv[i * 4] = *(const float4*)(qp + i * 4);
                    *(float4*)&vv[i * 4] = *(const float4*)(vp + i * 4);
                }
            } else {
                #pragma unroll
                for (int i = 0; i < 32; i++) { qv[i] = 0.f; vv[i] = 0.f; }
            }
            float ss = 0.f;
            #pragma unroll
            for (int i = 0; i < 32; i++) ss += qv[i] * qv[i];
            ss += __shfl_xor_sync(0xffffffff, ss, 1);
            float inv = 1.0f / fmaxf(sqrtf(ss), 1e-8f);

            unsigned eoff = (unsigned)t * 144 + half * 64;
            #pragma unroll
            for (int i = 0; i < 4; i++) {
                uint4 e, qb, vb;
                e.x = pack_bf16(qv[i*8+0]*inv, qv[i*8+1]*inv);
                e.y = pack_bf16(qv[i*8+2]*inv, qv[i*8+3]*inv);
                e.z = pack_bf16(qv[i*8+4]*inv, qv[i*8+5]*inv);
                e.w = pack_bf16(qv[i*8+6]*inv, qv[i*8+7]*inv);
                qb.x = pack_bf16(qv[i*8+0], qv[i*8+1]);
                qb.y = pack_bf16(qv[i*8+2], qv[i*8+3]);
                qb.z = pack_bf16(qv[i*8+4], qv[i*8+5]);
                qb.w = pack_bf16(qv[i*8+6], qv[i*8+7]);
                vb.x = pack_bf16(vv[i*8+0], vv[i*8+1]);
                vb.y = pack_bf16(vv[i*8+2], vv[i*8+3]);
                vb.z = pack_bf16(vv[i*8+4], vv[i*8+5]);
                vb.w = pack_bf16(vv[i*8+6], vv[i*8+7]);
                *(uint4*)(smem + G_QE + eoff + i * 16) = e;
                *(uint4*)(smem + G_QB + eoff + i * 16) = qb;
                *(uint4*)(smem + G_VB + eoff + i * 16) = vb;
            }
        }
        __syncthreads();

        // ---- MMA: warps 0-3 -> G (Qe,Qe); warps 4-7 -> U (Qb,Vb) ----
        const uint32_t Abase = sbase + ((wid < 4) ? G_QE : G_QB);
        const uint32_t Bbase = sbase + ((wid < 4) ? G_QE : G_VB);
        #pragma unroll
        for (int ks = 0; ks < 8; ks++) {
            uint32_t a0[4], a1[4];
            LDSM_X4_T(a0, Abase + (ks * 16 + krowA) * 144 + (mT + dcolA) * 2);
            LDSM_X4_T(a1, Abase + (ks * 16 + krowA) * 144 + (mT + 16 + dcolA) * 2);
            #pragma unroll
            for (int nt2 = 0; nt2 < 2; nt2++) {
                uint32_t bb[4];
                LDSM_X4_T(bb, Bbase + (ks * 16 + krowB) * 144 + (nT + nt2 * 16 + ncolB) * 2);
                MMA16816(acc[0][nt2 * 2],     a0, bb[0], bb[1]);
                MMA16816(acc[0][nt2 * 2 + 1], a0, bb[2], bb[3]);
                MMA16816(acc[1][nt2 * 2],     a1, bb[0], bb[1]);
                MMA16816(acc[1][nt2 * 2 + 1], a1, bb[2], bb[3]);
            }
        }
        __syncthreads();
    }

    // ---- accumulate into global ----
    float* dst = (wid < 4) ? g_G : g_U;
    dst += h * ND * ND;
    #pragma unroll
    for (int mi = 0; mi < 2; mi++)
        #pragma unroll
        for (int nj = 0; nj < 4; nj++) {
            int p = mT + mi * 16 + (lane >> 2);
            int r = nT + nj * 8 + (lane & 3) * 2;
            atomicAdd(dst + p * ND + r,           acc[mi][nj][0]);
            atomicAdd(dst + p * ND + r + 1,       acc[mi][nj][1]);
            atomicAdd(dst + (p + 8) * ND + r,     acc[mi][nj][2]);
            atomicAdd(dst + (p + 8) * ND + r + 1, acc[mi][nj][3]);
        }
}

// ---------------------------------------------------------------------------
// Kernel 2: T[h] = 0.99*trace - (0.99/denom)*G@trace + (0.1/denom)*U
// ---------------------------------------------------------------------------
__global__ __launch_bounds__(256) void combine_kernel(const float* __restrict__ trace) {
    const int h = blockIdx.x;
    const int tid = threadIdx.x;
    __shared__ float Gs[ND][ND];
    __shared__ float Ts[ND][ND];
    for (int i = tid; i < ND * ND; i += 256) {
        Gs[i >> 6][i & 63] = g_G[h * ND * ND + i];
        Ts[i >> 6][i & 63] = trace[h * ND * ND + i];
    }
    __syncthreads();
    const float denom = (float)NTOK;
    const float c0 = 0.99f;
    const float c1 = 0.99f / denom;
    const float c2 = 0.1f / denom;
    for (int o = tid; o < ND * ND; o += 256) {
        int p = o >> 6, q = o & 63;
        float s = 0.f;
        #pragma unroll
        for (int r = 0; r < ND; r++) s += Gs[p][r] * Ts[r][q];
        g_T[h * ND * ND + o] = c0 * Ts[p][q] - c1 * s + c2 * g_U[h * ND * ND + o];
    }
}

// ---------------------------------------------------------------------------
// Kernel 3: Wc[m][h*64+p] = sum_q T[h][p][q] * W_out[m][h*64+q], bf16 hi/lo.
// Register-tiled 64x64x64 GEMM per block. grid (H=8, NDM/64=12), block 256.
// ---------------------------------------------------------------------------
__global__ __launch_bounds__(256) void wc_kernel(const float* __restrict__ W_out) {
    const int h = blockIdx.x;
    const int mb = blockIdx.y * 64;
    const int tid = threadIdx.x;
    __shared__ float TsT[ND][ND + 4];   // [q][p]
    __shared__ float Ws[ND][ND + 4];    // [m][q]
    for (int i = tid; i < ND * ND; i += 256) {
        int p = i >> 6, q = i & 63;
        TsT[q][p] = g_T[h * ND * ND + i];
    }
    #pragma unroll
    for (int i = 0; i < 4; i++) {
        int fid = tid + i * 256;        // [0,1024) float4 slots
        int m = fid >> 4;
        int q4 = (fid & 15) << 2;
        *(float4*)&Ws[m][q4] =
            *(const float4*)(W_out + (long long)(mb + m) * HD + h * ND + q4);
    }
    __syncthreads();

    const int ty = tid >> 4, tx = tid & 15;   // m-tile, p-tile
    float acc[4][4] = {};
    #pragma unroll
    for (int q = 0; q < ND; q++) {
        float a[4], b[4];
        #pragma unroll
        for (int i = 0; i < 4; i++) a[i] = Ws[ty * 4 + i][q];
        *(float4*)b = *(float4*)&TsT[q][tx * 4];
        #pragma unroll
        for (int i = 0; i < 4; i++)
            #pragma unroll
            for (int j = 0; j < 4; j++) acc[i][j] += a[i] * b[j];
    }
    #pragma unroll
    for (int i = 0; i < 4; i++) {
        long long m = mb + ty * 4 + i;
        #pragma unroll
        for (int j = 0; j < 4; j++) {
            int p = tx * 4 + j;
            float s = acc[i][j];
            __nv_bfloat16 hi = __float2bfloat16_rn(s);
            __nv_bfloat16 lo = __float2bfloat16_rn(s - __bfloat162float(hi));
            g_WcHi[m * HD + h * ND + p] = hi;
            g_WcLo[m * HD + h * ND + p] = lo;
        }
    }
}

// ---------------------------------------------------------------------------
// Kernel 4: GEMM  out[r][n] = sum_k A[r][k]*Wc[n][k], bf16 split 3-product,
// fp32 acc. CTA 128x128, kb = 8 x K64. cp.async double-buffered.
// ---------------------------------------------------------------------------
#define TILE_B (128 * 144)          // one bf16 tile (128 rows x 64 k, pitch 144B)
#define ST_AH 0
#define ST_AL TILE_B
#define ST_BH (2 * TILE_B)
#define ST_BL (3 * TILE_B)
#define STAGE_B (4 * TILE_B)        // 73728
#define GEMM_SMEM (2 * STAGE_B)     // 147456

__device__ __forceinline__ void gemm_issue(uint32_t sdst, int kb, int mBase, int nBase,
                                           int tid) {
    // 4096 cp.async chunks of 16B: tile(2b) | row(7b) | seg(3b)
    #pragma unroll
    for (int i = 0; i < 16; i++) {
        int c = tid + i * 256;
        int tile = c >> 10;
        int row = (c >> 3) & 127;
        int seg = c & 7;
        uint32_t dst = sdst + tile * TILE_B + row * 144 + seg * 16;
        const __nv_bfloat16* src;
        if (tile == 0)      src = g_AHi + (long long)(mBase + row) * HD + kb * 64 + seg * 8;
        else if (tile == 1) src = g_ALo + (long long)(mBase + row) * HD + kb * 64 + seg * 8;
        else if (tile == 2) src = g_WcHi + (long long)(nBase + row) * HD + kb * 64 + seg * 8;
        else                src = g_WcLo + (long long)(nBase + row) * HD + kb * 64 + seg * 8;
        CP_ASYNC16(dst, src);
    }
}

__global__ void __launch_bounds__(256, 1) gemm_mma_kernel(float* __restrict__ out) {
    extern __shared__ char smem[];
    const uint32_t sbase = smem_to_u32(smem);
    const int tid = threadIdx.x;
    const int lane = tid & 31, wid = tid >> 5;
    const int warpM = (wid & 3) * 32;
    const int warpN = (wid >> 2) * 64;
    const int mBase = blockIdx.x * 128;
    const int nBase = blockIdx.y * 128;

    float acc[2][8][4] = {};

    const uint32_t aoff = (uint32_t)(warpM + (lane & 15)) * 144 + (lane >> 4) * 16;
    const uint32_t boff = (uint32_t)(warpN + ((lane >> 4) << 3) + (lane & 7)) * 144
                        + (((lane >> 3) & 1) * 16);

    gemm_issue(sbase, 0, mBase, nBase, tid);
    CP_COMMIT();

    #pragma unroll 1
    for (int kb = 0; kb < 8; kb++) {
        const uint32_t st = (kb & 1) * STAGE_B;
        if (kb < 7) {
            gemm_issue(sbase + ((kb + 1) & 1) * STAGE_B, kb + 1, mBase, nBase, tid);
            CP_COMMIT();
            CP_WAIT(1);
        } else {
            CP_WAIT(0);
        }
        __syncthreads();

        #pragma unroll
        for (int ks = 0; ks < 4; ks++) {
            uint32_t aH = sbase + st + ST_AH + aoff + ks * 32;
            uint32_t aL = sbase + st + ST_AL + aoff + ks * 32;
            uint32_t ah[2][4], al[2][4];
            LDSM_X4(ah[0], aH);
            LDSM_X4(ah[1], aH + 16 * 144);
            LDSM_X4(al[0], aL);
            LDSM_X4(al[1], aL + 16 * 144);
            #pragma unroll
            for (int nt = 0; nt < 4; nt++) {
                uint32_t bH = sbase + st + ST_BH + boff + ks * 32 + nt * 16 * 144;
                uint32_t bL = sbase + st + ST_BL + boff + ks * 32 + nt * 16 * 144;
                uint32_t bh[4], bl[4];
                LDSM_X4(bh, bH);
                LDSM_X4(bl, bL);
                #pragma unroll
                for (int mt = 0; mt < 2; mt++) {
                    MMA16816(acc[mt][2 * nt],     ah[mt], bh[0], bh[1]);
                    MMA16816(acc[mt][2 * nt + 1], ah[mt], bh[2], bh[3]);
                    MMA16816(acc[mt][2 * nt],     ah[mt], bl[0], bl[1]);
                    MMA16816(acc[mt][2 * nt + 1], ah[mt], bl[2], bl[3]);
                    MMA16816(acc[mt][2 * nt],     al[mt], bh[0], bh[1]);
                    MMA16816(acc[mt][2 * nt + 1], al[mt], bh[2], bh[3]);
                }
            }
        }
        __syncthreads();
    }

    #pragma unroll
    for (int mt = 0; mt < 2; mt++) {
        #pragma unroll
        for (int j = 0; j < 8; j++) {
            long long row = mBase + warpM + mt * 16 + (lane >> 2);
            int col = nBase + warpN + j * 8 + (lane & 3) * 2;
            float* o = out + row * NDM + col;
            *(float2*)o = make_float2(acc[mt][j][0], acc[mt][j][1]);
            *(float2*)(o + 8LL * NDM) = make_float2(acc[mt][j][2], acc[mt][j][3]);
        }
    }
}

// ---------------------------------------------------------------------------
extern "C" void kernel_launch(void* const* d_in, const int* in_sizes, int n_in,
                              void* d_out, int out_size) {
    const float* Q     = (const float*)d_in[0];
    const float* V     = (const float*)d_in[1];
    const float* trace = (const float*)d_in[2];
    const float* W_out = (const float*)d_in[3];
    float* out = (float*)d_out;

    cudaFuncSetAttribute(gram_tc_kernel,
                         cudaFuncAttributeMaxDynamicSharedMemorySize, GRAM_SMEM);
    cudaFuncSetAttribute(gemm_mma_kernel,
                         cudaFuncAttributeMaxDynamicSharedMemorySize, GEMM_SMEM);

    zero_kernel<<<(NH * ND * ND + 255) / 256, 256>>>();
    prep_a_kernel<<<(NROW * HD / 4) / 256, 256>>>(Q);
    {
        dim3 grid(32, NH);
        gram_tc_kernel<<<grid, 256, GRAM_SMEM>>>(Q, V);
    }
    combine_kernel<<<NH, 256>>>(trace);
    {
        dim3 grid(NH, NDM / 64);
        wc_kernel<<<grid, 256>>>(W_out);
    }
    {
        dim3 grid(NROW / 128, NDM / 128);
        gemm_mma_kernel<<<grid, 256, GEMM_SMEM>>>(out);
    }
}